// round 1
// baseline (speedup 1.0000x reference)
#include <cuda_runtime.h>
#include <cuda_bf16.h>
#include <math.h>

#define EDIM 768
#define NS 16
#define KC 4
#define RD 48
#define PD 80      // R + 2N
#define NDEPTH 4
#define VOC 32000
#define NB 2
#define LL 1024
#define HD 3072
#define BL (NB*LL)

// ---------------- scratch (device globals; no allocation allowed) ----------------
__device__ float g_x[BL*EDIM];
__device__ float g_xn[BL*EDIM];
__device__ float g_z[BL*EDIM];
__device__ float g_dt[BL*EDIM];
__device__ float g_u[BL*EDIM];
__device__ float g_y[BL*EDIM];
__device__ float g_params[BL*PD];
__device__ float g_hid[BL*HD];
__device__ float g_semb[NB*EDIM];
__device__ float g_thid[NB*HD];
__device__ float g_temb[NB*EDIM];

// ---------------- helpers ----------------
__device__ __forceinline__ float siluf(float x) { return x / (1.0f + expf(-x)); }
__device__ __forceinline__ float geluf(float x) { return 0.5f * x * (1.0f + erff(x * 0.7071067811865476f)); }
__device__ __forceinline__ float softplusf(float x) { return (x > 20.0f) ? x : log1pf(expf(x)); }

__device__ __forceinline__ float warpsum(float v) {
    #pragma unroll
    for (int o = 16; o > 0; o >>= 1) v += __shfl_down_sync(0xffffffffu, v, o);
    return v;
}

// ---------------- sinusoidal time embedding ----------------
__global__ void semb_kernel(const int* __restrict__ timesteps, float* __restrict__ semb) {
    int idx = blockIdx.x * blockDim.x + threadIdx.x;
    if (idx >= NB * EDIM) return;
    int b = idx / EDIM, e = idx % EDIM;
    const int half = EDIM / 2;
    float t = (float)timesteps[b];
    int j = (e < half) ? e : (e - half);
    float freq = expf(-9.210340371976184f * (float)j / (float)half); // ln(10000)
    float arg = t * freq;
    semb[idx] = (e < half) ? sinf(arg) : cosf(arg);
}

// hidden = silu(semb @ w1^T + b1), one warp per output
__global__ void time_mlp1(const float* __restrict__ w1, const float* __restrict__ b1,
                          const float* __restrict__ semb, float* __restrict__ thid) {
    int gw = (blockIdx.x * blockDim.x + threadIdx.x) >> 5;
    int ln = threadIdx.x & 31;
    if (gw >= NB * HD) return;
    int b = gw / HD, hh = gw % HD;
    const float* e = semb + b * EDIM;
    const float* w = w1 + (size_t)hh * EDIM;
    float s = 0.f;
    for (int k = ln; k < EDIM; k += 32) s += e[k] * w[k];
    s = warpsum(s);
    if (ln == 0) { s += b1[hh]; thid[gw] = siluf(s); }
}

// temb = thid @ w2^T + b2
__global__ void time_mlp2(const float* __restrict__ w2, const float* __restrict__ b2,
                          const float* __restrict__ thid, float* __restrict__ temb) {
    int gw = (blockIdx.x * blockDim.x + threadIdx.x) >> 5;
    int ln = threadIdx.x & 31;
    if (gw >= NB * EDIM) return;
    int b = gw / EDIM, e = gw % EDIM;
    const float* h = thid + b * HD;
    const float* w = w2 + (size_t)e * HD;
    float s = 0.f;
    for (int k = ln; k < HD; k += 32) s += h[k] * w[k];
    s = warpsum(s);
    if (ln == 0) temb[gw] = s + b2[e];
}

// x = tok_emb[tokens] + temb
__global__ void embed_kernel(const int* __restrict__ tokens, const float* __restrict__ tok_emb,
                             const float* __restrict__ temb, float* __restrict__ x) {
    int idx = blockIdx.x * blockDim.x + threadIdx.x;
    if (idx >= BL * EDIM) return;
    int e = idx % EDIM, bl = idx / EDIM, b = bl / LL;
    int tok = tokens[bl];
    x[idx] = tok_emb[(size_t)tok * EDIM + e] + temb[b * EDIM + e];
}

// ---------------- layernorm (one block per row) ----------------
__global__ void ln_kernel(const float* __restrict__ in, float* __restrict__ out,
                          const float* __restrict__ g, const float* __restrict__ bia) {
    int row = blockIdx.x;
    const float* x = in + (size_t)row * EDIM;
    float s = 0.f, s2 = 0.f;
    for (int e = threadIdx.x; e < EDIM; e += blockDim.x) { float v = x[e]; s += v; s2 += v * v; }
    __shared__ float sh1[8], sh2[8];
    __shared__ float smu, srs;
    int w = threadIdx.x >> 5, ln = threadIdx.x & 31;
    s = warpsum(s); s2 = warpsum(s2);
    if (ln == 0) { sh1[w] = s; sh2[w] = s2; }
    __syncthreads();
    if (threadIdx.x == 0) {
        float a = 0.f, c = 0.f;
        #pragma unroll
        for (int i = 0; i < 8; i++) { a += sh1[i]; c += sh2[i]; }
        float mu = a / EDIM;
        float var = c / EDIM - mu * mu;
        smu = mu; srs = rsqrtf(var + 1e-5f);
    }
    __syncthreads();
    float mu = smu, rs = srs;
    float* o = out + (size_t)row * EDIM;
    for (int e = threadIdx.x; e < EDIM; e += blockDim.x)
        o[e] = (x[e] - mu) * rs * g[e] + bia[e];
}

// ---------------- depthwise causal conv + silu ----------------
__global__ void conv_silu(const float* __restrict__ xn, const float* __restrict__ w,
                          float* __restrict__ u) {
    int idx = blockIdx.x * blockDim.x + threadIdx.x;
    if (idx >= BL * EDIM) return;
    int e = idx % EDIM, bl = idx / EDIM, l = bl % LL, b = bl / LL;
    const float* base = xn + (size_t)b * LL * EDIM + e;
    float acc = 0.f;
    #pragma unroll
    for (int k = 0; k < KC; k++) {
        int ls = l - (KC - 1) + k;
        if (ls >= 0) acc += base[(size_t)ls * EDIM] * w[e * KC + k];
    }
    u[idx] = siluf(acc);
}

// ---------------- SSM selective scan: one thread per (b, e) ----------------
__global__ void scan_kernel(const float* __restrict__ Alog, const float* __restrict__ Dp,
                            const float* __restrict__ dt, const float* __restrict__ u,
                            const float* __restrict__ params, float* __restrict__ y) {
    int idx = blockIdx.x * blockDim.x + threadIdx.x;
    if (idx >= NB * EDIM) return;
    int b = idx / EDIM, e = idx % EDIM;

    float a[NS], invA[NS];
    bool small[NS];
    #pragma unroll
    for (int n = 0; n < NS; n++) {
        float av = -expf(Alog[(size_t)e * NS + n]);
        a[n] = av;
        invA[n] = 1.0f / (av + 1e-10f);
        small[n] = fabsf(av) < 1e-5f;
    }
    float D = Dp[e];

    const float* dtp = dt + (size_t)b * LL * EDIM + e;
    const float* up  = u  + (size_t)b * LL * EDIM + e;
    const float* cpp = params + (size_t)b * LL * PD + (RD + NS); // Cp offset 64
    float* yp = y + (size_t)b * LL * EDIM + e;

    float h[NS];
    #pragma unroll
    for (int n = 0; n < NS; n++) h[n] = 0.f;

    float dt_prev = 0.f, u_prev = 0.f;
    for (int l = 0; l < LL; l++) {
        float dt_l = dtp[(size_t)l * EDIM];
        float u_l  = up[(size_t)l * EDIM];
        float dd = (l == 0) ? dt_l : dt_prev;
        float uu = (l == 0) ? u_l  : u_prev;
        if (l == 0) {
            #pragma unroll
            for (int n = 0; n < NS; n++) {
                float At = __expf(dd * a[n]);
                float Bt = small[n] ? dd : (At - 1.0f) * invA[n];
                h[n] = Bt * uu;
            }
        } else {
            #pragma unroll
            for (int n = 0; n < NS; n++) {
                float At = __expf(dd * a[n]);
                float Bt = small[n] ? dd : (At - 1.0f) * invA[n];
                h[n] = At * h[n] + Bt * uu;
            }
        }
        const float4* cp4 = (const float4*)(cpp + (size_t)l * PD);
        float4 c0 = cp4[0], c1 = cp4[1], c2 = cp4[2], c3 = cp4[3];
        float cr[NS] = {c0.x,c0.y,c0.z,c0.w, c1.x,c1.y,c1.z,c1.w,
                        c2.x,c2.y,c2.z,c2.w, c3.x,c3.y,c3.z,c3.w};
        float yy = 0.f;
        #pragma unroll
        for (int n = 0; n < NS; n++) yy += cr[n] * h[n];
        yp[(size_t)l * EDIM] = yy + u_l * D;
        dt_prev = dt_l; u_prev = u_l;
    }
}

// ---------------- y *= silu(z) ----------------
__global__ void smul_kernel(float* __restrict__ y, const float* __restrict__ z) {
    int idx = blockIdx.x * blockDim.x + threadIdx.x;
    if (idx >= BL * EDIM) return;
    y[idx] = y[idx] * siluf(z[idx]);
}

// ---------------- generic SGEMM: C[m,n] = sum_k A[m,k] * B[n,k] (+bias)(+act)(+=C) ----
// BM=BN=128, BK=8, 256 threads, 8x8 per-thread microtile. M must be a multiple of 128,
// K a multiple of 8, N a multiple of 4.
template<int ACT, bool BIAS, bool ACC>
__global__ void __launch_bounds__(256) gemm_tn(
    const float* __restrict__ A, int lda,
    const float* __restrict__ Bm, int ldb,
    const float* __restrict__ bias,
    float* __restrict__ C, int ldc,
    int M, int N, int K)
{
    __shared__ float As[8][132];
    __shared__ float Bs[8][132];
    int tid = threadIdx.x;
    int bm = blockIdx.y, bn = blockIdx.x;
    int tx = tid % 16, ty = tid / 16;

    float acc[8][8];
    #pragma unroll
    for (int i = 0; i < 8; i++)
        #pragma unroll
        for (int j = 0; j < 8; j++) acc[i][j] = 0.f;

    int ar = tid >> 1;
    int ak = (tid & 1) * 4;
    const float* Ab = A + (size_t)(bm * 128 + ar) * lda + ak;
    int brow = bn * 128 + ar;
    const float* Bb = Bm + (size_t)brow * ldb + ak;
    bool bvalid = brow < N;

    for (int k0 = 0; k0 < K; k0 += 8) {
        float4 av = *(const float4*)(Ab + k0);
        float4 bv = bvalid ? *(const float4*)(Bb + k0) : make_float4(0.f,0.f,0.f,0.f);
        As[ak+0][ar] = av.x; As[ak+1][ar] = av.y; As[ak+2][ar] = av.z; As[ak+3][ar] = av.w;
        Bs[ak+0][ar] = bv.x; Bs[ak+1][ar] = bv.y; Bs[ak+2][ar] = bv.z; Bs[ak+3][ar] = bv.w;
        __syncthreads();
        #pragma unroll
        for (int kk = 0; kk < 8; kk++) {
            float4 a0 = *(const float4*)(&As[kk][ty*8]);
            float4 a1 = *(const float4*)(&As[kk][ty*8+4]);
            float4 b0 = *(const float4*)(&Bs[kk][tx*8]);
            float4 b1 = *(const float4*)(&Bs[kk][tx*8+4]);
            float arf[8] = {a0.x,a0.y,a0.z,a0.w,a1.x,a1.y,a1.z,a1.w};
            float brf[8] = {b0.x,b0.y,b0.z,b0.w,b1.x,b1.y,b1.z,b1.w};
            #pragma unroll
            for (int i = 0; i < 8; i++)
                #pragma unroll
                for (int j = 0; j < 8; j++)
                    acc[i][j] = fmaf(arf[i], brf[j], acc[i][j]);
        }
        __syncthreads();
    }

    int row0 = bm * 128 + ty * 8;
    int col0 = bn * 128 + tx * 8;
    #pragma unroll
    for (int i = 0; i < 8; i++) {
        float* Crow = C + (size_t)(row0 + i) * ldc;
        #pragma unroll
        for (int jv = 0; jv < 8; jv += 4) {
            int col = col0 + jv;
            if (col < N) {
                float4 v = make_float4(acc[i][jv], acc[i][jv+1], acc[i][jv+2], acc[i][jv+3]);
                if (BIAS) {
                    v.x += bias[col]; v.y += bias[col+1]; v.z += bias[col+2]; v.w += bias[col+3];
                }
                if (ACT == 1) { v.x = softplusf(v.x); v.y = softplusf(v.y); v.z = softplusf(v.z); v.w = softplusf(v.w); }
                if (ACT == 2) { v.x = geluf(v.x); v.y = geluf(v.y); v.z = geluf(v.z); v.w = geluf(v.w); }
                if (ACC) {
                    float4 old = *(const float4*)(&Crow[col]);
                    v.x += old.x; v.y += old.y; v.z += old.z; v.w += old.w;
                }
                *(float4*)(&Crow[col]) = v;
            }
        }
    }
}

// ---------------- launch ----------------
extern "C" void kernel_launch(void* const* d_in, const int* in_sizes, int n_in,
                              void* d_out, int out_size) {
    const int*   tokens    = (const int*)  d_in[0];
    const int*   timesteps = (const int*)  d_in[1];
    const float* tok_emb   = (const float*)d_in[2];
    const float* time_w1   = (const float*)d_in[3];
    const float* time_b1   = (const float*)d_in[4];
    const float* time_w2   = (const float*)d_in[5];
    const float* time_b2   = (const float*)d_in[6];
    const float* ln1_g     = (const float*)d_in[7];
    const float* ln1_b     = (const float*)d_in[8];
    const float* z_w       = (const float*)d_in[9];
    const float* p_w       = (const float*)d_in[10];
    const float* conv_w    = (const float*)d_in[11];
    const float* dtp_w     = (const float*)d_in[12];
    const float* dtp_b     = (const float*)d_in[13];
    const float* A_log     = (const float*)d_in[14];
    const float* D_param   = (const float*)d_in[15];
    const float* out_w     = (const float*)d_in[16];
    const float* ln2_g     = (const float*)d_in[17];
    const float* ln2_b     = (const float*)d_in[18];
    const float* mlp_w1    = (const float*)d_in[19];
    const float* mlp_b1    = (const float*)d_in[20];
    const float* mlp_w2    = (const float*)d_in[21];
    const float* mlp_b2    = (const float*)d_in[22];
    const float* lnout_g   = (const float*)d_in[23];
    const float* lnout_b   = (const float*)d_in[24];
    const float* head_w    = (const float*)d_in[25];
    const float* head_b    = (const float*)d_in[26];

    void *p_x, *p_xn, *p_z, *p_dt, *p_u, *p_y, *p_params, *p_hid, *p_semb, *p_thid, *p_temb;
    cudaGetSymbolAddress(&p_x, g_x);
    cudaGetSymbolAddress(&p_xn, g_xn);
    cudaGetSymbolAddress(&p_z, g_z);
    cudaGetSymbolAddress(&p_dt, g_dt);
    cudaGetSymbolAddress(&p_u, g_u);
    cudaGetSymbolAddress(&p_y, g_y);
    cudaGetSymbolAddress(&p_params, g_params);
    cudaGetSymbolAddress(&p_hid, g_hid);
    cudaGetSymbolAddress(&p_semb, g_semb);
    cudaGetSymbolAddress(&p_thid, g_thid);
    cudaGetSymbolAddress(&p_temb, g_temb);
    float* bx = (float*)p_x;       float* bxn = (float*)p_xn;
    float* bz = (float*)p_z;       float* bdt = (float*)p_dt;
    float* bu = (float*)p_u;       float* by  = (float*)p_y;
    float* bparams = (float*)p_params; float* bhid = (float*)p_hid;
    float* bsemb = (float*)p_semb; float* bthid = (float*)p_thid;
    float* btemb = (float*)p_temb;

    // time embedding
    semb_kernel<<<(NB*EDIM + 255)/256, 256>>>(timesteps, bsemb);
    time_mlp1<<<(NB*HD*32 + 255)/256, 256>>>(time_w1, time_b1, bsemb, bthid);
    time_mlp2<<<(NB*EDIM*32 + 255)/256, 256>>>(time_w2, time_b2, bthid, btemb);
    embed_kernel<<<(BL*EDIM + 255)/256, 256>>>(tokens, tok_emb, btemb, bx);

    dim3 gb(256);
    for (int i = 0; i < NDEPTH; i++) {
        const float* zwi   = z_w   + (size_t)i * EDIM * EDIM;
        const float* pwi   = p_w   + (size_t)i * PD * EDIM;
        const float* cwi   = conv_w+ (size_t)i * EDIM * KC;
        const float* dtwi  = dtp_w + (size_t)i * EDIM * RD;
        const float* dtbi  = dtp_b + (size_t)i * EDIM;
        const float* ali   = A_log + (size_t)i * EDIM * NS;
        const float* dpi   = D_param + (size_t)i * EDIM;
        const float* owi   = out_w + (size_t)i * EDIM * EDIM;
        const float* w1i   = mlp_w1+ (size_t)i * HD * EDIM;
        const float* b1i   = mlp_b1+ (size_t)i * HD;
        const float* w2i   = mlp_w2+ (size_t)i * EDIM * HD;
        const float* b2i   = mlp_b2+ (size_t)i * EDIM;

        ln_kernel<<<BL, 256>>>(bx, bxn, ln1_g + i*EDIM, ln1_b + i*EDIM);
        gemm_tn<0,false,false><<<dim3(EDIM/128, BL/128), gb>>>(bxn, EDIM, zwi, EDIM, nullptr, bz, EDIM, BL, EDIM, EDIM);
        gemm_tn<0,false,false><<<dim3(1, BL/128), gb>>>(bxn, EDIM, pwi, EDIM, nullptr, bparams, PD, BL, PD, EDIM);
        gemm_tn<1,true,false><<<dim3(EDIM/128, BL/128), gb>>>(bparams, PD, dtwi, RD, dtbi, bdt, EDIM, BL, EDIM, RD);
        conv_silu<<<(BL*EDIM + 255)/256, 256>>>(bxn, cwi, bu);
        scan_kernel<<<(NB*EDIM + 255)/256, 256>>>(ali, dpi, bdt, bu, bparams, by);
        smul_kernel<<<(BL*EDIM + 255)/256, 256>>>(by, bz);
        gemm_tn<0,false,true><<<dim3(EDIM/128, BL/128), gb>>>(by, EDIM, owi, EDIM, nullptr, bx, EDIM, BL, EDIM, EDIM);
        ln_kernel<<<BL, 256>>>(bx, bxn, ln2_g + i*EDIM, ln2_b + i*EDIM);
        gemm_tn<2,true,false><<<dim3(HD/128, BL/128), gb>>>(bxn, EDIM, w1i, EDIM, b1i, bhid, HD, BL, HD, EDIM);
        gemm_tn<0,true,true><<<dim3(EDIM/128, BL/128), gb>>>(bhid, HD, w2i, HD, b2i, bx, EDIM, BL, EDIM, HD);
    }

    ln_kernel<<<BL, 256>>>(bx, bxn, lnout_g, lnout_b);
    gemm_tn<0,true,false><<<dim3(VOC/128, BL/128), gb>>>(bxn, EDIM, head_w, EDIM, head_b,
                                                         (float*)d_out, VOC, BL, VOC, EDIM);
}

// round 3
// speedup vs baseline: 1.5889x; 1.5889x over previous
#include <cuda_runtime.h>
#include <cuda_bf16.h>
#include <math.h>
#include <stdint.h>

#define EDIM 768
#define NS 16
#define KC 4
#define RD 48
#define PD 80      // R + 2N
#define NDEPTH 4
#define VOC 32000
#define NB 2
#define LL 1024
#define HD 3072
#define BL (NB*LL)

// ---------------- scratch (device globals; no allocation allowed) ----------------
__device__ float g_x[BL*EDIM];
__device__ float g_xn[BL*EDIM];
__device__ float g_z[BL*EDIM];
__device__ float g_dt[BL*EDIM];
__device__ float g_u[BL*EDIM];
__device__ float g_y[BL*EDIM];
__device__ float g_params[BL*PD];
__device__ float g_hid[BL*HD];
__device__ float g_semb[NB*EDIM];
__device__ float g_thid[NB*HD];
__device__ float g_temb[NB*EDIM];
__device__ float g_pw_pad[NDEPTH*128*EDIM];

// ---------------- helpers ----------------
__device__ __forceinline__ float siluf(float x) { return x / (1.0f + expf(-x)); }
__device__ __forceinline__ float geluf(float x) { return 0.5f * x * (1.0f + erff(x * 0.7071067811865476f)); }
__device__ __forceinline__ float softplusf(float x) { return (x > 20.0f) ? x : log1pf(expf(x)); }

__device__ __forceinline__ float warpsum(float v) {
    #pragma unroll
    for (int o = 16; o > 0; o >>= 1) v += __shfl_down_sync(0xffffffffu, v, o);
    return v;
}

__device__ __forceinline__ uint32_t smem_to_u32(const void* smem_ptr) {
    uint32_t addr;
    asm("{ .reg .u64 tmp; cvta.to.shared.u64 tmp, %1; cvt.u32.u64 %0, tmp; }"
        : "=r"(addr) : "l"(smem_ptr));
    return addr;
}

__device__ __forceinline__ void ldsm_x4(uint32_t& r0, uint32_t& r1, uint32_t& r2, uint32_t& r3,
                                        uint32_t addr) {
    asm volatile("ldmatrix.sync.aligned.m8n8.x4.shared.b16 {%0,%1,%2,%3}, [%4];"
                 : "=r"(r0), "=r"(r1), "=r"(r2), "=r"(r3) : "r"(addr));
}

__device__ __forceinline__ void mma16816(float* c, const uint32_t* a, uint32_t b0, uint32_t b1) {
    asm volatile(
        "mma.sync.aligned.m16n8k16.row.col.f32.bf16.bf16.f32 "
        "{%0,%1,%2,%3}, {%4,%5,%6,%7}, {%8,%9}, {%0,%1,%2,%3};\n"
        : "+f"(c[0]), "+f"(c[1]), "+f"(c[2]), "+f"(c[3])
        : "r"(a[0]), "r"(a[1]), "r"(a[2]), "r"(a[3]), "r"(b0), "r"(b1));
}

__device__ __forceinline__ uint32_t pack_bf16_hi(float x, float y) {
    __nv_bfloat16 hx = __float2bfloat16_rn(x);
    __nv_bfloat16 hy = __float2bfloat16_rn(y);
    return (uint32_t)__bfloat16_as_ushort(hx) | ((uint32_t)__bfloat16_as_ushort(hy) << 16);
}

// ---------------- sinusoidal time embedding ----------------
__global__ void semb_kernel(const int* __restrict__ timesteps, float* __restrict__ semb) {
    int idx = blockIdx.x * blockDim.x + threadIdx.x;
    if (idx >= NB * EDIM) return;
    int b = idx / EDIM, e = idx % EDIM;
    const int half = EDIM / 2;
    float t = (float)timesteps[b];
    int j = (e < half) ? e : (e - half);
    float freq = expf(-9.210340371976184f * (float)j / (float)half);
    float arg = t * freq;
    semb[idx] = (e < half) ? sinf(arg) : cosf(arg);
}

__global__ void time_mlp1(const float* __restrict__ w1, const float* __restrict__ b1,
                          const float* __restrict__ semb, float* __restrict__ thid) {
    int gw = (blockIdx.x * blockDim.x + threadIdx.x) >> 5;
    int ln = threadIdx.x & 31;
    if (gw >= NB * HD) return;
    int b = gw / HD, hh = gw % HD;
    const float* e = semb + b * EDIM;
    const float* w = w1 + (size_t)hh * EDIM;
    float s = 0.f;
    for (int k = ln; k < EDIM; k += 32) s += e[k] * w[k];
    s = warpsum(s);
    if (ln == 0) { s += b1[hh]; thid[gw] = siluf(s); }
}

__global__ void time_mlp2(const float* __restrict__ w2, const float* __restrict__ b2,
                          const float* __restrict__ thid, float* __restrict__ temb) {
    int gw = (blockIdx.x * blockDim.x + threadIdx.x) >> 5;
    int ln = threadIdx.x & 31;
    if (gw >= NB * EDIM) return;
    int b = gw / EDIM, e = gw % EDIM;
    const float* h = thid + b * HD;
    const float* w = w2 + (size_t)e * HD;
    float s = 0.f;
    for (int k = ln; k < HD; k += 32) s += h[k] * w[k];
    s = warpsum(s);
    if (ln == 0) temb[gw] = s + b2[e];
}

__global__ void embed_kernel(const int* __restrict__ tokens, const float* __restrict__ tok_emb,
                             const float* __restrict__ temb, float* __restrict__ x) {
    int idx = blockIdx.x * blockDim.x + threadIdx.x;
    if (idx >= BL * EDIM) return;
    int e = idx % EDIM, bl = idx / EDIM, b = bl / LL;
    int tok = tokens[bl];
    x[idx] = tok_emb[(size_t)tok * EDIM + e] + temb[b * EDIM + e];
}

// pad p_w (DEPTH,80,768) -> (DEPTH,128,768) zero-filled
__global__ void pad_pw_kernel(const float* __restrict__ p_w, float* __restrict__ dst) {
    int idx = blockIdx.x * blockDim.x + threadIdx.x;
    if (idx >= NDEPTH * 128 * EDIM) return;
    int c = idx % EDIM;
    int r = (idx / EDIM) % 128;
    int d = idx / (128 * EDIM);
    dst[idx] = (r < PD) ? p_w[((size_t)d * PD + r) * EDIM + c] : 0.f;
}

// ---------------- layernorm ----------------
__global__ void ln_kernel(const float* __restrict__ in, float* __restrict__ out,
                          const float* __restrict__ g, const float* __restrict__ bia) {
    int row = blockIdx.x;
    const float* x = in + (size_t)row * EDIM;
    float s = 0.f, s2 = 0.f;
    for (int e = threadIdx.x; e < EDIM; e += blockDim.x) { float v = x[e]; s += v; s2 += v * v; }
    __shared__ float sh1[8], sh2[8];
    __shared__ float smu, srs;
    int w = threadIdx.x >> 5, ln = threadIdx.x & 31;
    s = warpsum(s); s2 = warpsum(s2);
    if (ln == 0) { sh1[w] = s; sh2[w] = s2; }
    __syncthreads();
    if (threadIdx.x == 0) {
        float a = 0.f, c = 0.f;
        #pragma unroll
        for (int i = 0; i < 8; i++) { a += sh1[i]; c += sh2[i]; }
        float mu = a / EDIM;
        float var = c / EDIM - mu * mu;
        smu = mu; srs = rsqrtf(var + 1e-5f);
    }
    __syncthreads();
    float mu = smu, rs = srs;
    float* o = out + (size_t)row * EDIM;
    for (int e = threadIdx.x; e < EDIM; e += blockDim.x)
        o[e] = (x[e] - mu) * rs * g[e] + bia[e];
}

// ---------------- depthwise causal conv + silu ----------------
__global__ void conv_silu(const float* __restrict__ xn, const float* __restrict__ w,
                          float* __restrict__ u) {
    int idx = blockIdx.x * blockDim.x + threadIdx.x;
    if (idx >= BL * EDIM) return;
    int e = idx % EDIM, bl = idx / EDIM, l = bl % LL, b = bl / LL;
    const float* base = xn + (size_t)b * LL * EDIM + e;
    float acc = 0.f;
    #pragma unroll
    for (int k = 0; k < KC; k++) {
        int ls = l - (KC - 1) + k;
        if (ls >= 0) acc += base[(size_t)ls * EDIM] * w[e * KC + k];
    }
    u[idx] = siluf(acc);
}

// ---------------- SSM scan: one thread per (b, e, n); 16-lane reduction over n ----
__global__ void scan_kernel(const float* __restrict__ Alog, const float* __restrict__ Dp,
                            const float* __restrict__ dt, const float* __restrict__ u,
                            const float* __restrict__ params, const float* __restrict__ z,
                            float* __restrict__ y) {
    int g = blockIdx.x * blockDim.x + threadIdx.x;
    if (g >= NB * EDIM * NS) return;
    int n = g & (NS - 1);
    int pe = g >> 4;
    int e = pe % EDIM, b = pe / EDIM;

    float av = -expf(Alog[(size_t)e * NS + n]);
    float invA = 1.0f / (av + 1e-10f);
    bool smallA = fabsf(av) < 1e-5f;
    float D = Dp[e];

    const float* dtp = dt + (size_t)b * LL * EDIM + e;
    const float* up  = u  + (size_t)b * LL * EDIM + e;
    const float* zp  = z  + (size_t)b * LL * EDIM + e;
    const float* cpp = params + (size_t)b * LL * PD + (RD + NS) + n;
    float* yp = y + (size_t)b * LL * EDIM + e;

    float h = 0.f, ddp = 0.f, uup = 0.f;
    for (int l = 0; l < LL; l++) {
        float dtl = dtp[(size_t)l * EDIM];
        float ul  = up[(size_t)l * EDIM];
        float dd = (l == 0) ? dtl : ddp;
        float uu = (l == 0) ? ul  : uup;
        float At = __expf(dd * av);
        float Bt = smallA ? dd : (At - 1.0f) * invA;
        h = fmaf(At, h, Bt * uu);
        float c = cpp[(size_t)l * PD];
        float yy = c * h;
        yy += __shfl_xor_sync(0xffffffffu, yy, 1);
        yy += __shfl_xor_sync(0xffffffffu, yy, 2);
        yy += __shfl_xor_sync(0xffffffffu, yy, 4);
        yy += __shfl_xor_sync(0xffffffffu, yy, 8);
        if (n == 0) {
            float zl = zp[(size_t)l * EDIM];
            yp[(size_t)l * EDIM] = (yy + ul * D) * siluf(zl);
        }
        ddp = dtl; uup = ul;
    }
}

// ---------------- SIMT GEMM (kept for dt: K=48) -------
template<int ACT, bool BIAS, bool ACC>
__global__ void __launch_bounds__(256) gemm_tn(
    const float* __restrict__ A, int lda,
    const float* __restrict__ Bm, int ldb,
    const float* __restrict__ bias,
    float* __restrict__ C, int ldc,
    int M, int N, int K)
{
    __shared__ float As[8][132];
    __shared__ float Bs[8][132];
    int tid = threadIdx.x;
    int bm = blockIdx.y, bn = blockIdx.x;
    int tx = tid % 16, ty = tid / 16;

    float acc[8][8];
    #pragma unroll
    for (int i = 0; i < 8; i++)
        #pragma unroll
        for (int j = 0; j < 8; j++) acc[i][j] = 0.f;

    int ar = tid >> 1;
    int ak = (tid & 1) * 4;
    const float* Ab = A + (size_t)(bm * 128 + ar) * lda + ak;
    int brow = bn * 128 + ar;
    const float* Bb = Bm + (size_t)brow * ldb + ak;
    bool bvalid = brow < N;

    for (int k0 = 0; k0 < K; k0 += 8) {
        float4 av = *(const float4*)(Ab + k0);
        float4 bv = bvalid ? *(const float4*)(Bb + k0) : make_float4(0.f,0.f,0.f,0.f);
        As[ak+0][ar] = av.x; As[ak+1][ar] = av.y; As[ak+2][ar] = av.z; As[ak+3][ar] = av.w;
        Bs[ak+0][ar] = bv.x; Bs[ak+1][ar] = bv.y; Bs[ak+2][ar] = bv.z; Bs[ak+3][ar] = bv.w;
        __syncthreads();
        #pragma unroll
        for (int kk = 0; kk < 8; kk++) {
            float4 a0 = *(const float4*)(&As[kk][ty*8]);
            float4 a1 = *(const float4*)(&As[kk][ty*8+4]);
            float4 b0 = *(const float4*)(&Bs[kk][tx*8]);
            float4 b1 = *(const float4*)(&Bs[kk][tx*8+4]);
            float arf[8] = {a0.x,a0.y,a0.z,a0.w,a1.x,a1.y,a1.z,a1.w};
            float brf[8] = {b0.x,b0.y,b0.z,b0.w,b1.x,b1.y,b1.z,b1.w};
            #pragma unroll
            for (int i = 0; i < 8; i++)
                #pragma unroll
                for (int j = 0; j < 8; j++)
                    acc[i][j] = fmaf(arf[i], brf[j], acc[i][j]);
        }
        __syncthreads();
    }

    int row0 = bm * 128 + ty * 8;
    int col0 = bn * 128 + tx * 8;
    #pragma unroll
    for (int i = 0; i < 8; i++) {
        float* Crow = C + (size_t)(row0 + i) * ldc;
        #pragma unroll
        for (int jv = 0; jv < 8; jv += 4) {
            int col = col0 + jv;
            if (col < N) {
                float4 v = make_float4(acc[i][jv], acc[i][jv+1], acc[i][jv+2], acc[i][jv+3]);
                if (BIAS) {
                    v.x += bias[col]; v.y += bias[col+1]; v.z += bias[col+2]; v.w += bias[col+3];
                }
                if (ACT == 1) { v.x = softplusf(v.x); v.y = softplusf(v.y); v.z = softplusf(v.z); v.w = softplusf(v.w); }
                if (ACT == 2) { v.x = geluf(v.x); v.y = geluf(v.y); v.z = geluf(v.z); v.w = geluf(v.w); }
                if (ACC) {
                    float4 old = *(const float4*)(&Crow[col]);
                    v.x += old.x; v.y += old.y; v.z += old.z; v.w += old.w;
                }
                *(float4*)(&Crow[col]) = v;
            }
        }
    }
}

// ================= mma.sync bf16 split GEMM =================
// C[m,n] = sum_k A[m,k]*B[n,k]  (fp32 in/out; bf16 hi/lo 3-term split internally)
// CTA tile 128x128, K-chunk 32, 256 threads (8 warps: 2(m) x 4(n), warp tile 64x32).
// Requires M%128==0, K%32==0, lda/ldb%4==0. N handled via nmax guard (cols are
// written in 8-wide tiles; nmax must be a multiple of 8).

__device__ __forceinline__ void cvt_store_pair(uint32_t base_hi, uint32_t base_lo,
                                               int r, int c4, float4 v) {
    uint32_t h0 = pack_bf16_hi(v.x, v.y);
    uint32_t h1 = pack_bf16_hi(v.z, v.w);
    float rx = v.x - __bfloat162float(__float2bfloat16_rn(v.x));
    float ry = v.y - __bfloat162float(__float2bfloat16_rn(v.y));
    float rz = v.z - __bfloat162float(__float2bfloat16_rn(v.z));
    float rw = v.w - __bfloat162float(__float2bfloat16_rn(v.w));
    uint32_t l0 = pack_bf16_hi(rx, ry);
    uint32_t l1 = pack_bf16_hi(rz, rw);
    uint32_t off = (uint32_t)(r * 64) + ((((uint32_t)c4 >> 1) ^ (((uint32_t)r >> 1) & 3u)) << 4)
                 + (((uint32_t)c4 & 1u) << 3);
    asm volatile("st.shared.v2.b32 [%0], {%1,%2};" :: "r"(base_hi + off), "r"(h0), "r"(h1) : "memory");
    asm volatile("st.shared.v2.b32 [%0], {%1,%2};" :: "r"(base_lo + off), "r"(l0), "r"(l1) : "memory");
}

template<int ACT, bool BIAS, bool ACC>
__global__ void __launch_bounds__(256) gemm_mma(
    const float* __restrict__ A, int lda,
    const float* __restrict__ B, int ldb,
    const float* __restrict__ bias,
    float* __restrict__ C, int ldc,
    int K, int nmax)
{
    __shared__ __align__(16) unsigned char smem_raw[32768];
    uint32_t sb = smem_to_u32(smem_raw);
    const uint32_t sAh = sb, sAl = sb + 8192, sBh = sb + 16384, sBl = sb + 24576;

    int tid = threadIdx.x;
    int wid = tid >> 5, lid = tid & 31;
    int wm = wid & 1, wn = wid >> 1;

    const float* Abase = A + (size_t)(blockIdx.y * 128) * lda;
    const float* Bbase = B + (size_t)(blockIdx.x * 128) * ldb;

    float acc[4][4][4];
    #pragma unroll
    for (int i = 0; i < 4; i++)
        #pragma unroll
        for (int j = 0; j < 4; j++)
            #pragma unroll
            for (int q = 0; q < 4; q++) acc[i][j][q] = 0.f;

    int r0 = tid >> 3;       // 0..31 (row base; +32 per iteration)
    int c4 = tid & 7;        // float4 column within the 32-wide chunk

    float4 rA[4], rB[4];
    #pragma unroll
    for (int it = 0; it < 4; it++) {
        rA[it] = *(const float4*)(Abase + (size_t)(r0 + it * 32) * lda + c4 * 4);
        rB[it] = *(const float4*)(Bbase + (size_t)(r0 + it * 32) * ldb + c4 * 4);
    }

    int NC = K / 32;
    for (int c = 0; c < NC; c++) {
        #pragma unroll
        for (int it = 0; it < 4; it++) {
            cvt_store_pair(sAh, sAl, r0 + it * 32, c4, rA[it]);
            cvt_store_pair(sBh, sBl, r0 + it * 32, c4, rB[it]);
        }
        __syncthreads();
        if (c + 1 < NC) {
            int koff = (c + 1) * 32 + c4 * 4;
            #pragma unroll
            for (int it = 0; it < 4; it++) {
                rA[it] = *(const float4*)(Abase + (size_t)(r0 + it * 32) * lda + koff);
                rB[it] = *(const float4*)(Bbase + (size_t)(r0 + it * 32) * ldb + koff);
            }
        }
        #pragma unroll
        for (int ks = 0; ks < 2; ks++) {
            // B fragments: 2 ldsm.x4 per precision cover all 4 n8-tiles
            uint32_t bh[2][4], bl_[2][4];
            #pragma unroll
            for (int j2 = 0; j2 < 2; j2++) {
                int mrow = wn * 32 + j2 * 16 + ((lid >> 3) & 1) * 8 + (lid & 7);
                int kch = 2 * ks + (lid >> 4);
                uint32_t off = (uint32_t)(mrow * 64)
                             + (((uint32_t)kch ^ (((uint32_t)mrow >> 1) & 3u)) << 4);
                ldsm_x4(bh[j2][0], bh[j2][1], bh[j2][2], bh[j2][3], sBh + off);
                ldsm_x4(bl_[j2][0], bl_[j2][1], bl_[j2][2], bl_[j2][3], sBl + off);
            }
            #pragma unroll
            for (int i = 0; i < 4; i++) {
                int arow = wm * 64 + i * 16 + (lid & 15);
                int kch = 2 * ks + (lid >> 4);
                uint32_t off = (uint32_t)(arow * 64)
                             + (((uint32_t)kch ^ (((uint32_t)arow >> 1) & 3u)) << 4);
                uint32_t ah[4], al[4];
                ldsm_x4(ah[0], ah[1], ah[2], ah[3], sAh + off);
                ldsm_x4(al[0], al[1], al[2], al[3], sAl + off);
                #pragma unroll
                for (int j = 0; j < 4; j++) {
                    int j2 = j >> 1, js = j & 1;
                    mma16816(acc[i][j], ah, bh[j2][js], bh[j2][2 + js]);
                    mma16816(acc[i][j], ah, bl_[j2][js], bl_[j2][2 + js]);
                    mma16816(acc[i][j], al, bh[j2][js], bh[j2][2 + js]);
                }
            }
        }
        __syncthreads();
    }

    // epilogue
    int lr = lid >> 2;
    int lc = (lid & 3) * 2;
    #pragma unroll
    for (int i = 0; i < 4; i++) {
        int row = blockIdx.y * 128 + wm * 64 + i * 16 + lr;
        #pragma unroll
        for (int j = 0; j < 4; j++) {
            int col0 = blockIdx.x * 128 + wn * 32 + j * 8 + lc;
            if (col0 < nmax) {
                #pragma unroll
                for (int half = 0; half < 2; half++) {
                    int rr = row + half * 8;
                    float v0 = acc[i][j][half * 2 + 0];
                    float v1 = acc[i][j][half * 2 + 1];
                    if (BIAS) { v0 += bias[col0]; v1 += bias[col0 + 1]; }
                    if (ACT == 1) { v0 = softplusf(v0); v1 = softplusf(v1); }
                    if (ACT == 2) { v0 = geluf(v0); v1 = geluf(v1); }
                    float* cp = C + (size_t)rr * ldc + col0;
                    if (ACC) {
                        float2 old = *(const float2*)cp;
                        v0 += old.x; v1 += old.y;
                    }
                    *(float2*)cp = make_float2(v0, v1);
                }
            }
        }
    }
}

// ---------------- launch ----------------
extern "C" void kernel_launch(void* const* d_in, const int* in_sizes, int n_in,
                              void* d_out, int out_size) {
    const int*   tokens    = (const int*)  d_in[0];
    const int*   timesteps = (const int*)  d_in[1];
    const float* tok_emb   = (const float*)d_in[2];
    const float* time_w1   = (const float*)d_in[3];
    const float* time_b1   = (const float*)d_in[4];
    const float* time_w2   = (const float*)d_in[5];
    const float* time_b2   = (const float*)d_in[6];
    const float* ln1_g     = (const float*)d_in[7];
    const float* ln1_b     = (const float*)d_in[8];
    const float* z_w       = (const float*)d_in[9];
    const float* p_w       = (const float*)d_in[10];
    const float* conv_w    = (const float*)d_in[11];
    const float* dtp_w     = (const float*)d_in[12];
    const float* dtp_b     = (const float*)d_in[13];
    const float* A_log     = (const float*)d_in[14];
    const float* D_param   = (const float*)d_in[15];
    const float* out_w     = (const float*)d_in[16];
    const float* ln2_g     = (const float*)d_in[17];
    const float* ln2_b     = (const float*)d_in[18];
    const float* mlp_w1    = (const float*)d_in[19];
    const float* mlp_b1    = (const float*)d_in[20];
    const float* mlp_w2    = (const float*)d_in[21];
    const float* mlp_b2    = (const float*)d_in[22];
    const float* lnout_g   = (const float*)d_in[23];
    const float* lnout_b   = (const float*)d_in[24];
    const float* head_w    = (const float*)d_in[25];
    const float* head_b    = (const float*)d_in[26];

    void *p_x, *p_xn, *p_z, *p_dt, *p_u, *p_y, *p_params, *p_hid, *p_semb, *p_thid, *p_temb, *p_pwp;
    cudaGetSymbolAddress(&p_x, g_x);
    cudaGetSymbolAddress(&p_xn, g_xn);
    cudaGetSymbolAddress(&p_z, g_z);
    cudaGetSymbolAddress(&p_dt, g_dt);
    cudaGetSymbolAddress(&p_u, g_u);
    cudaGetSymbolAddress(&p_y, g_y);
    cudaGetSymbolAddress(&p_params, g_params);
    cudaGetSymbolAddress(&p_hid, g_hid);
    cudaGetSymbolAddress(&p_semb, g_semb);
    cudaGetSymbolAddress(&p_thid, g_thid);
    cudaGetSymbolAddress(&p_temb, g_temb);
    cudaGetSymbolAddress(&p_pwp, g_pw_pad);
    float* bx = (float*)p_x;       float* bxn = (float*)p_xn;
    float* bz = (float*)p_z;       float* bdt = (float*)p_dt;
    float* bu = (float*)p_u;       float* by  = (float*)p_y;
    float* bparams = (float*)p_params; float* bhid = (float*)p_hid;
    float* bsemb = (float*)p_semb; float* bthid = (float*)p_thid;
    float* btemb = (float*)p_temb; float* bpwp = (float*)p_pwp;

    // time embedding + input embed
    semb_kernel<<<(NB*EDIM + 255)/256, 256>>>(timesteps, bsemb);
    time_mlp1<<<(NB*HD*32 + 255)/256, 256>>>(time_w1, time_b1, bsemb, bthid);
    time_mlp2<<<(NB*EDIM*32 + 255)/256, 256>>>(time_w2, time_b2, bthid, btemb);
    embed_kernel<<<(BL*EDIM + 255)/256, 256>>>(tokens, tok_emb, btemb, bx);
    pad_pw_kernel<<<(NDEPTH*128*EDIM + 255)/256, 256>>>(p_w, bpwp);

    dim3 gb(256);
    for (int i = 0; i < NDEPTH; i++) {
        const float* zwi   = z_w   + (size_t)i * EDIM * EDIM;
        const float* pwi   = bpwp  + (size_t)i * 128 * EDIM;
        const float* cwi   = conv_w+ (size_t)i * EDIM * KC;
        const float* dtwi  = dtp_w + (size_t)i * EDIM * RD;
        const float* dtbi  = dtp_b + (size_t)i * EDIM;
        const float* ali   = A_log + (size_t)i * EDIM * NS;
        const float* dpi   = D_param + (size_t)i * EDIM;
        const float* owi   = out_w + (size_t)i * EDIM * EDIM;
        const float* w1i   = mlp_w1+ (size_t)i * HD * EDIM;
        const float* b1i   = mlp_b1+ (size_t)i * HD;
        const float* w2i   = mlp_w2+ (size_t)i * EDIM * HD;
        const float* b2i   = mlp_b2+ (size_t)i * EDIM;

        ln_kernel<<<BL, 256>>>(bx, bxn, ln1_g + i*EDIM, ln1_b + i*EDIM);
        // z = xn @ z_w^T
        gemm_mma<0,false,false><<<dim3(EDIM/128, BL/128), gb>>>(
            bxn, EDIM, zwi, EDIM, nullptr, bz, EDIM, EDIM, EDIM);
        // params = xn @ p_w^T (padded B, nmax=80)
        gemm_mma<0,false,false><<<dim3(1, BL/128), gb>>>(
            bxn, EDIM, pwi, EDIM, nullptr, bparams, PD, EDIM, PD);
        // dt = softplus(params[:, :48] @ dtp_w^T + b)  (SIMT, K=48)
        gemm_tn<1,true,false><<<dim3(EDIM/128, BL/128), gb>>>(
            bparams, PD, dtwi, RD, dtbi, bdt, EDIM, BL, EDIM, RD);
        conv_silu<<<(BL*EDIM + 255)/256, 256>>>(bxn, cwi, bu);
        // scan (fuses silu(z) gating)
        scan_kernel<<<(NB*EDIM*NS + 255)/256, 256>>>(ali, dpi, bdt, bu, bparams, bz, by);
        // x += y @ out_w^T
        gemm_mma<0,false,true><<<dim3(EDIM/128, BL/128), gb>>>(
            by, EDIM, owi, EDIM, nullptr, bx, EDIM, EDIM, EDIM);
        ln_kernel<<<BL, 256>>>(bx, bxn, ln2_g + i*EDIM, ln2_b + i*EDIM);
        // hid = gelu(xn @ w1^T + b1)
        gemm_mma<2,true,false><<<dim3(HD/128, BL/128), gb>>>(
            bxn, EDIM, w1i, EDIM, b1i, bhid, HD, EDIM, HD);
        // x += hid @ w2^T + b2
        gemm_mma<0,true,true><<<dim3(EDIM/128, BL/128), gb>>>(
            bhid, HD, w2i, HD, b2i, bx, EDIM, HD, EDIM);
    }

    ln_kernel<<<BL, 256>>>(bx, bxn, lnout_g, lnout_b);
    // logits = xn @ head_w^T + head_b
    gemm_mma<0,true,false><<<dim3(VOC/128, BL/128), gb>>>(
        bxn, EDIM, head_w, EDIM, head_b, (float*)d_out, VOC, EDIM, VOC);
}

// round 4
// speedup vs baseline: 1.6912x; 1.0644x over previous
#include <cuda_runtime.h>
#include <cuda_bf16.h>
#include <math.h>
#include <stdint.h>

#define EDIM 768
#define NS 16
#define KC 4
#define RD 48
#define PD 80      // R + 2N
#define ZPN 896    // fused z(768) + padded params(128)
#define NDEPTH 4
#define VOC 32000
#define NB 2
#define LL 1024
#define HD 3072
#define BL (NB*LL)

typedef __nv_bfloat16 bf16;

// ---------------- scratch (device globals) ----------------
__device__ __align__(16) float g_x[BL*EDIM];
__device__ __align__(16) float g_xn[BL*EDIM];
__device__ __align__(16) float g_zp[BL*ZPN];
__device__ __align__(16) float g_dt[BL*EDIM];
__device__ __align__(16) float g_u[BL*EDIM];
__device__ __align__(16) float g_semb[NB*EDIM];
__device__ __align__(16) float g_thid[NB*HD];
__device__ __align__(16) float g_temb[NB*EDIM];

// bf16 hi/lo activation buffers
__device__ __align__(16) bf16 g_xnh[BL*EDIM];
__device__ __align__(16) bf16 g_xnl[BL*EDIM];
__device__ __align__(16) bf16 g_yh[BL*EDIM];
__device__ __align__(16) bf16 g_yl[BL*EDIM];
__device__ __align__(16) bf16 g_hidh[BL*HD];
__device__ __align__(16) bf16 g_hidl[BL*HD];

// bf16 hi/lo weight buffers (converted once per call)
__device__ __align__(16) bf16 g_wzp_h[NDEPTH*ZPN*EDIM];
__device__ __align__(16) bf16 g_wzp_l[NDEPTH*ZPN*EDIM];
__device__ __align__(16) bf16 g_wout_h[NDEPTH*EDIM*EDIM];
__device__ __align__(16) bf16 g_wout_l[NDEPTH*EDIM*EDIM];
__device__ __align__(16) bf16 g_wm1_h[NDEPTH*HD*EDIM];
__device__ __align__(16) bf16 g_wm1_l[NDEPTH*HD*EDIM];
__device__ __align__(16) bf16 g_wm2_h[NDEPTH*EDIM*HD];
__device__ __align__(16) bf16 g_wm2_l[NDEPTH*EDIM*HD];
__device__ __align__(16) bf16 g_whd_h[(size_t)VOC*EDIM];
__device__ __align__(16) bf16 g_whd_l[(size_t)VOC*EDIM];

// ---------------- helpers ----------------
__device__ __forceinline__ float siluf(float x) { return x / (1.0f + expf(-x)); }
__device__ __forceinline__ float geluf(float x) { return 0.5f * x * (1.0f + erff(x * 0.7071067811865476f)); }
__device__ __forceinline__ float softplusf(float x) { return (x > 20.0f) ? x : log1pf(expf(x)); }

__device__ __forceinline__ float warpsum(float v) {
    #pragma unroll
    for (int o = 16; o > 0; o >>= 1) v += __shfl_down_sync(0xffffffffu, v, o);
    return v;
}

__device__ __forceinline__ uint32_t smem_to_u32(const void* smem_ptr) {
    uint32_t addr;
    asm("{ .reg .u64 tmp; cvta.to.shared.u64 tmp, %1; cvt.u32.u64 %0, tmp; }"
        : "=r"(addr) : "l"(smem_ptr));
    return addr;
}

__device__ __forceinline__ void ldsm_x4(uint32_t& r0, uint32_t& r1, uint32_t& r2, uint32_t& r3,
                                        uint32_t addr) {
    asm volatile("ldmatrix.sync.aligned.m8n8.x4.shared.b16 {%0,%1,%2,%3}, [%4];"
                 : "=r"(r0), "=r"(r1), "=r"(r2), "=r"(r3) : "r"(addr));
}

__device__ __forceinline__ void mma16816(float* c, const uint32_t* a, uint32_t b0, uint32_t b1) {
    asm volatile(
        "mma.sync.aligned.m16n8k16.row.col.f32.bf16.bf16.f32 "
        "{%0,%1,%2,%3}, {%4,%5,%6,%7}, {%8,%9}, {%0,%1,%2,%3};\n"
        : "+f"(c[0]), "+f"(c[1]), "+f"(c[2]), "+f"(c[3])
        : "r"(a[0]), "r"(a[1]), "r"(a[2]), "r"(a[3]), "r"(b0), "r"(b1));
}

#define CP_ASYNC16(dst, src) \
    asm volatile("cp.async.cg.shared.global [%0], [%1], 16;" :: "r"(dst), "l"(src) : "memory")
#define CP_COMMIT() asm volatile("cp.async.commit_group;" ::: "memory")
#define CP_WAIT(n)  asm volatile("cp.async.wait_group %0;" :: "n"(n) : "memory")

// ---------------- weight conversion ----------------
__global__ void cvt_split_kernel(const float* __restrict__ src, bf16* __restrict__ h,
                                 bf16* __restrict__ l, size_t n) {
    size_t i = (size_t)blockIdx.x * blockDim.x + threadIdx.x;
    if (i >= n) return;
    float v = src[i];
    bf16 hv = __float2bfloat16_rn(v);
    h[i] = hv;
    l[i] = __float2bfloat16_rn(v - __bfloat162float(hv));
}

// fused z_w + padded p_w weight: per depth [z_w(768 rows); p_w(80 rows); zeros(48)]
__global__ void build_wzp_kernel(const float* __restrict__ z_w, const float* __restrict__ p_w,
                                 bf16* __restrict__ h, bf16* __restrict__ l) {
    size_t i = (size_t)blockIdx.x * blockDim.x + threadIdx.x;
    if (i >= (size_t)NDEPTH * ZPN * EDIM) return;
    int c = i % EDIM;
    int r = (i / EDIM) % ZPN;
    int d = i / ((size_t)ZPN * EDIM);
    float v;
    if (r < EDIM)            v = z_w[((size_t)d * EDIM + r) * EDIM + c];
    else if (r - EDIM < PD)  v = p_w[((size_t)d * PD + (r - EDIM)) * EDIM + c];
    else                     v = 0.f;
    bf16 hv = __float2bfloat16_rn(v);
    h[i] = hv;
    l[i] = __float2bfloat16_rn(v - __bfloat162float(hv));
}

// ---------------- time embedding ----------------
__global__ void semb_kernel(const int* __restrict__ timesteps, float* __restrict__ semb) {
    int idx = blockIdx.x * blockDim.x + threadIdx.x;
    if (idx >= NB * EDIM) return;
    int b = idx / EDIM, e = idx % EDIM;
    const int half = EDIM / 2;
    float t = (float)timesteps[b];
    int j = (e < half) ? e : (e - half);
    float freq = expf(-9.210340371976184f * (float)j / (float)half);
    float arg = t * freq;
    semb[idx] = (e < half) ? sinf(arg) : cosf(arg);
}

__global__ void time_mlp1(const float* __restrict__ w1, const float* __restrict__ b1,
                          const float* __restrict__ semb, float* __restrict__ thid) {
    int gw = (blockIdx.x * blockDim.x + threadIdx.x) >> 5;
    int ln = threadIdx.x & 31;
    if (gw >= NB * HD) return;
    int b = gw / HD, hh = gw % HD;
    const float* e = semb + b * EDIM;
    const float* w = w1 + (size_t)hh * EDIM;
    float s = 0.f;
    for (int k = ln; k < EDIM; k += 32) s += e[k] * w[k];
    s = warpsum(s);
    if (ln == 0) { s += b1[hh]; thid[gw] = siluf(s); }
}

__global__ void time_mlp2(const float* __restrict__ w2, const float* __restrict__ b2,
                          const float* __restrict__ thid, float* __restrict__ temb) {
    int gw = (blockIdx.x * blockDim.x + threadIdx.x) >> 5;
    int ln = threadIdx.x & 31;
    if (gw >= NB * EDIM) return;
    int b = gw / EDIM, e = gw % EDIM;
    const float* h = thid + b * HD;
    const float* w = w2 + (size_t)e * HD;
    float s = 0.f;
    for (int k = ln; k < HD; k += 32) s += h[k] * w[k];
    s = warpsum(s);
    if (ln == 0) temb[gw] = s + b2[e];
}

__global__ void embed_kernel(const int* __restrict__ tokens, const float* __restrict__ tok_emb,
                             const float* __restrict__ temb, float* __restrict__ x) {
    int idx = blockIdx.x * blockDim.x + threadIdx.x;
    if (idx >= BL * EDIM) return;
    int e = idx % EDIM, bl = idx / EDIM, b = bl / LL;
    int tok = tokens[bl];
    x[idx] = tok_emb[(size_t)tok * EDIM + e] + temb[b * EDIM + e];
}

// ---------------- layernorm: fp32 out + bf16 hi/lo out ----------------
__global__ void ln_kernel(const float* __restrict__ in, float* __restrict__ out,
                          bf16* __restrict__ oh, bf16* __restrict__ ol,
                          const float* __restrict__ g, const float* __restrict__ bia) {
    int row = blockIdx.x;
    const float* x = in + (size_t)row * EDIM;
    float s = 0.f, s2 = 0.f;
    for (int e = threadIdx.x; e < EDIM; e += blockDim.x) { float v = x[e]; s += v; s2 += v * v; }
    __shared__ float sh1[8], sh2[8];
    __shared__ float smu, srs;
    int w = threadIdx.x >> 5, ln = threadIdx.x & 31;
    s = warpsum(s); s2 = warpsum(s2);
    if (ln == 0) { sh1[w] = s; sh2[w] = s2; }
    __syncthreads();
    if (threadIdx.x == 0) {
        float a = 0.f, c = 0.f;
        #pragma unroll
        for (int i = 0; i < 8; i++) { a += sh1[i]; c += sh2[i]; }
        float mu = a / EDIM;
        float var = c / EDIM - mu * mu;
        smu = mu; srs = rsqrtf(var + 1e-5f);
    }
    __syncthreads();
    float mu = smu, rs = srs;
    float* o = out + (size_t)row * EDIM;
    bf16* ph = oh + (size_t)row * EDIM;
    bf16* pl = ol + (size_t)row * EDIM;
    for (int e = threadIdx.x; e < EDIM; e += blockDim.x) {
        float v = (x[e] - mu) * rs * g[e] + bia[e];
        o[e] = v;
        bf16 hv = __float2bfloat16_rn(v);
        ph[e] = hv;
        pl[e] = __float2bfloat16_rn(v - __bfloat162float(hv));
    }
}

// ---------------- depthwise causal conv + silu ----------------
__global__ void conv_silu(const float* __restrict__ xn, const float* __restrict__ w,
                          float* __restrict__ u) {
    int idx = blockIdx.x * blockDim.x + threadIdx.x;
    if (idx >= BL * EDIM) return;
    int e = idx % EDIM, bl = idx / EDIM, l = bl % LL, b = bl / LL;
    const float* base = xn + (size_t)b * LL * EDIM + e;
    float acc = 0.f;
    #pragma unroll
    for (int k = 0; k < KC; k++) {
        int ls = l - (KC - 1) + k;
        if (ls >= 0) acc += base[(size_t)ls * EDIM] * w[e * KC + k];
    }
    u[idx] = siluf(acc);
}

// ---------------- SSM scan: one thread per (b,e,n); outputs bf16 hi/lo ----------
__global__ void scan_kernel(const float* __restrict__ Alog, const float* __restrict__ Dp,
                            const float* __restrict__ dt, const float* __restrict__ u,
                            const float* __restrict__ zp,
                            bf16* __restrict__ yh, bf16* __restrict__ yl) {
    int g = blockIdx.x * blockDim.x + threadIdx.x;
    if (g >= NB * EDIM * NS) return;
    int n = g & (NS - 1);
    int pe = g >> 4;
    int e = pe % EDIM, b = pe / EDIM;

    float av = -expf(Alog[(size_t)e * NS + n]);
    float invA = 1.0f / (av + 1e-10f);
    bool smallA = fabsf(av) < 1e-5f;
    float D = Dp[e];

    const float* dtp = dt + (size_t)b * LL * EDIM + e;
    const float* up  = u  + (size_t)b * LL * EDIM + e;
    const float* zb  = zp + (size_t)b * LL * ZPN;       // fused buffer
    const float* cpp = zb + EDIM + RD + NS + n;         // Cp
    const float* zgp = zb + e;                          // z gate
    bf16* yph = yh + (size_t)b * LL * EDIM + e;
    bf16* ypl = yl + (size_t)b * LL * EDIM + e;

    float h = 0.f, ddp = 0.f, uup = 0.f;
    for (int l = 0; l < LL; l++) {
        float dtl = dtp[(size_t)l * EDIM];
        float ul  = up[(size_t)l * EDIM];
        float dd = (l == 0) ? dtl : ddp;
        float uu = (l == 0) ? ul  : uup;
        float At = __expf(dd * av);
        float Bt = smallA ? dd : (At - 1.0f) * invA;
        h = fmaf(At, h, Bt * uu);
        float c = cpp[(size_t)l * ZPN];
        float yy = c * h;
        yy += __shfl_xor_sync(0xffffffffu, yy, 1);
        yy += __shfl_xor_sync(0xffffffffu, yy, 2);
        yy += __shfl_xor_sync(0xffffffffu, yy, 4);
        yy += __shfl_xor_sync(0xffffffffu, yy, 8);
        if (n == 0) {
            float zl = zgp[(size_t)l * ZPN];
            float v = (yy + ul * D) * siluf(zl);
            bf16 hv = __float2bfloat16_rn(v);
            yph[(size_t)l * EDIM] = hv;
            ypl[(size_t)l * EDIM] = __float2bfloat16_rn(v - __bfloat162float(hv));
        }
        ddp = dtl; uup = ul;
    }
}

// ---------------- SIMT GEMM (dt projection: K=48) -------
template<int ACT, bool BIAS, bool ACC>
__global__ void __launch_bounds__(256) gemm_tn(
    const float* __restrict__ A, int lda,
    const float* __restrict__ Bm, int ldb,
    const float* __restrict__ bias,
    float* __restrict__ C, int ldc,
    int M, int N, int K)
{
    __shared__ float As[8][132];
    __shared__ float Bs[8][132];
    int tid = threadIdx.x;
    int bm = blockIdx.y, bn = blockIdx.x;
    int tx = tid % 16, ty = tid / 16;

    float acc[8][8];
    #pragma unroll
    for (int i = 0; i < 8; i++)
        #pragma unroll
        for (int j = 0; j < 8; j++) acc[i][j] = 0.f;

    int ar = tid >> 1;
    int ak = (tid & 1) * 4;
    const float* Ab = A + (size_t)(bm * 128 + ar) * lda + ak;
    int brow = bn * 128 + ar;
    const float* Bb = Bm + (size_t)brow * ldb + ak;
    bool bvalid = brow < N;

    for (int k0 = 0; k0 < K; k0 += 8) {
        float4 av = *(const float4*)(Ab + k0);
        float4 bv = bvalid ? *(const float4*)(Bb + k0) : make_float4(0.f,0.f,0.f,0.f);
        As[ak+0][ar] = av.x; As[ak+1][ar] = av.y; As[ak+2][ar] = av.z; As[ak+3][ar] = av.w;
        Bs[ak+0][ar] = bv.x; Bs[ak+1][ar] = bv.y; Bs[ak+2][ar] = bv.z; Bs[ak+3][ar] = bv.w;
        __syncthreads();
        #pragma unroll
        for (int kk = 0; kk < 8; kk++) {
            float4 a0 = *(const float4*)(&As[kk][ty*8]);
            float4 a1 = *(const float4*)(&As[kk][ty*8+4]);
            float4 b0 = *(const float4*)(&Bs[kk][tx*8]);
            float4 b1 = *(const float4*)(&Bs[kk][tx*8+4]);
            float arf[8] = {a0.x,a0.y,a0.z,a0.w,a1.x,a1.y,a1.z,a1.w};
            float brf[8] = {b0.x,b0.y,b0.z,b0.w,b1.x,b1.y,b1.z,b1.w};
            #pragma unroll
            for (int i = 0; i < 8; i++)
                #pragma unroll
                for (int j = 0; j < 8; j++)
                    acc[i][j] = fmaf(arf[i], brf[j], acc[i][j]);
        }
        __syncthreads();
    }

    int row0 = bm * 128 + ty * 8;
    int col0 = bn * 128 + tx * 8;
    #pragma unroll
    for (int i = 0; i < 8; i++) {
        float* Crow = C + (size_t)(row0 + i) * ldc;
        #pragma unroll
        for (int jv = 0; jv < 8; jv += 4) {
            int col = col0 + jv;
            if (col < N) {
                float4 v = make_float4(acc[i][jv], acc[i][jv+1], acc[i][jv+2], acc[i][jv+3]);
                if (BIAS) {
                    v.x += bias[col]; v.y += bias[col+1]; v.z += bias[col+2]; v.w += bias[col+3];
                }
                if (ACT == 1) { v.x = softplusf(v.x); v.y = softplusf(v.y); v.z = softplusf(v.z); v.w = softplusf(v.w); }
                if (ACT == 2) { v.x = geluf(v.x); v.y = geluf(v.y); v.z = geluf(v.z); v.w = geluf(v.w); }
                if (ACC) {
                    float4 old = *(const float4*)(&Crow[col]);
                    v.x += old.x; v.y += old.y; v.z += old.z; v.w += old.w;
                }
                *(float4*)(&Crow[col]) = v;
            }
        }
    }
}

// ================= bf16 hi/lo mma GEMM with cp.async double buffering =========
// C[m,n] = sum_k A[m,k]*B[n,k]; A, B given as bf16 hi/lo pairs (ld = K).
// CTA tile 128x128, K-chunk 32, 8 warps (2m x 4n, warp tile 64x32), 3-term split.
// grid.x = M/128 (fastest -> CTAs share B tile), grid.y = N blocks.
// OUT: 0 = store f32, 1 = accumulate f32, 2 = store bf16 hi/lo.

#define GSTAGE 32768
#define GSMEM  (2*GSTAGE)

__device__ __forceinline__ void g_load_stage(
    uint32_t st, const bf16* __restrict__ Ah, const bf16* __restrict__ Al,
    const bf16* __restrict__ Bh, const bf16* __restrict__ Bl,
    int K, int koff, int tid)
{
    int r = tid >> 1;
    int gb = (tid & 1) * 2;
    size_t ro = (size_t)r * K + koff;
    #pragma unroll
    for (int gi = 0; gi < 2; gi++) {
        int g = gb + gi;
        uint32_t so = (uint32_t)(r * 64 + ((g ^ ((r >> 1) & 3)) << 4));
        CP_ASYNC16(st + so,         Ah + ro + g * 8);
        CP_ASYNC16(st + 8192 + so,  Al + ro + g * 8);
        CP_ASYNC16(st + 16384 + so, Bh + ro + g * 8);
        CP_ASYNC16(st + 24576 + so, Bl + ro + g * 8);
    }
}

template<int ACT, bool BIAS, int OUT>
__global__ void __launch_bounds__(256) gemm_bf(
    const bf16* __restrict__ Ah, const bf16* __restrict__ Al,
    const bf16* __restrict__ Bh, const bf16* __restrict__ Bl,
    int K, const float* __restrict__ bias,
    float* __restrict__ C, bf16* __restrict__ Ch, bf16* __restrict__ Cl,
    int ldc, int nmax)
{
    extern __shared__ __align__(16) unsigned char smem_raw[];
    uint32_t sb = smem_to_u32(smem_raw);

    int tid = threadIdx.x;
    int wid = tid >> 5, lid = tid & 31;
    int wm = wid & 1, wn = wid >> 1;

    const bf16* Ah0 = Ah + (size_t)(blockIdx.x * 128) * K;
    const bf16* Al0 = Al + (size_t)(blockIdx.x * 128) * K;
    const bf16* Bh0 = Bh + (size_t)(blockIdx.y * 128) * K;
    const bf16* Bl0 = Bl + (size_t)(blockIdx.y * 128) * K;

    float acc[4][4][4];
    #pragma unroll
    for (int i = 0; i < 4; i++)
        #pragma unroll
        for (int j = 0; j < 4; j++)
            #pragma unroll
            for (int q = 0; q < 4; q++) acc[i][j][q] = 0.f;

    int NC = K / 32;
    g_load_stage(sb, Ah0, Al0, Bh0, Bl0, K, 0, tid);
    CP_COMMIT();

    for (int c = 0; c < NC; c++) {
        if (c + 1 < NC) {
            g_load_stage(sb + ((c + 1) & 1) * GSTAGE, Ah0, Al0, Bh0, Bl0, K, (c + 1) * 32, tid);
            CP_COMMIT();
            CP_WAIT(1);
        } else {
            CP_WAIT(0);
        }
        __syncthreads();

        uint32_t st = sb + (c & 1) * GSTAGE;
        uint32_t sAh = st, sAl = st + 8192, sBh = st + 16384, sBl = st + 24576;

        #pragma unroll
        for (int ks = 0; ks < 2; ks++) {
            uint32_t bh[2][4], bl_[2][4];
            #pragma unroll
            for (int j2 = 0; j2 < 2; j2++) {
                int mrow = wn * 32 + j2 * 16 + ((lid >> 3) & 1) * 8 + (lid & 7);
                int kch = 2 * ks + (lid >> 4);
                uint32_t off = (uint32_t)(mrow * 64)
                             + (((uint32_t)kch ^ (((uint32_t)mrow >> 1) & 3u)) << 4);
                ldsm_x4(bh[j2][0], bh[j2][1], bh[j2][2], bh[j2][3], sBh + off);
                ldsm_x4(bl_[j2][0], bl_[j2][1], bl_[j2][2], bl_[j2][3], sBl + off);
            }
            #pragma unroll
            for (int i = 0; i < 4; i++) {
                int arow = wm * 64 + i * 16 + (lid & 15);
                int kch = 2 * ks + (lid >> 4);
                uint32_t off = (uint32_t)(arow * 64)
                             + (((uint32_t)kch ^ (((uint32_t)arow >> 1) & 3u)) << 4);
                uint32_t ah[4], al[4];
                ldsm_x4(ah[0], ah[1], ah[2], ah[3], sAh + off);
                ldsm_x4(al[0], al[1], al[2], al[3], sAl + off);
                #pragma unroll
                for (int j = 0; j < 4; j++) {
                    int j2 = j >> 1, js = j & 1;
                    mma16816(acc[i][j], ah, bh[j2][js], bh[j2][2 + js]);
                    mma16816(acc[i][j], ah, bl_[j2][js], bl_[j2][2 + js]);
                    mma16816(acc[i][j], al, bh[j2][js], bh[j2][2 + js]);
                }
            }
        }
        __syncthreads();
    }

    // epilogue
    int lr = lid >> 2;
    int lc = (lid & 3) * 2;
    #pragma unroll
    for (int i = 0; i < 4; i++) {
        int row = blockIdx.x * 128 + wm * 64 + i * 16 + lr;
        #pragma unroll
        for (int j = 0; j < 4; j++) {
            int col0 = blockIdx.y * 128 + wn * 32 + j * 8 + lc;
            if (col0 < nmax) {
                #pragma unroll
                for (int half = 0; half < 2; half++) {
                    int rr = row + half * 8;
                    float v0 = acc[i][j][half * 2 + 0];
                    float v1 = acc[i][j][half * 2 + 1];
                    if (BIAS) { v0 += bias[col0]; v1 += bias[col0 + 1]; }
                    if (ACT == 1) { v0 = softplusf(v0); v1 = softplusf(v1); }
                    if (ACT == 2) { v0 = geluf(v0); v1 = geluf(v1); }
                    if (OUT == 2) {
                        bf16 h0 = __float2bfloat16_rn(v0);
                        bf16 h1 = __float2bfloat16_rn(v1);
                        bf16 l0 = __float2bfloat16_rn(v0 - __bfloat162float(h0));
                        bf16 l1 = __float2bfloat16_rn(v1 - __bfloat162float(h1));
                        __nv_bfloat162* ph = (__nv_bfloat162*)(Ch + (size_t)rr * ldc + col0);
                        __nv_bfloat162* pl = (__nv_bfloat162*)(Cl + (size_t)rr * ldc + col0);
                        *ph = __nv_bfloat162(h0, h1);
                        *pl = __nv_bfloat162(l0, l1);
                    } else {
                        float* cp = C + (size_t)rr * ldc + col0;
                        if (OUT == 1) {
                            float2 old = *(const float2*)cp;
                            v0 += old.x; v1 += old.y;
                        }
                        *(float2*)cp = make_float2(v0, v1);
                    }
                }
            }
        }
    }
}

// ---------------- launch ----------------
extern "C" void kernel_launch(void* const* d_in, const int* in_sizes, int n_in,
                              void* d_out, int out_size) {
    const int*   tokens    = (const int*)  d_in[0];
    const int*   timesteps = (const int*)  d_in[1];
    const float* tok_emb   = (const float*)d_in[2];
    const float* time_w1   = (const float*)d_in[3];
    const float* time_b1   = (const float*)d_in[4];
    const float* time_w2   = (const float*)d_in[5];
    const float* time_b2   = (const float*)d_in[6];
    const float* ln1_g     = (const float*)d_in[7];
    const float* ln1_b     = (const float*)d_in[8];
    const float* z_w       = (const float*)d_in[9];
    const float* p_w       = (const float*)d_in[10];
    const float* conv_w    = (const float*)d_in[11];
    const float* dtp_w     = (const float*)d_in[12];
    const float* dtp_b     = (const float*)d_in[13];
    const float* A_log     = (const float*)d_in[14];
    const float* D_param   = (const float*)d_in[15];
    const float* out_w     = (const float*)d_in[16];
    const float* ln2_g     = (const float*)d_in[17];
    const float* ln2_b     = (const float*)d_in[18];
    const float* mlp_w1    = (const float*)d_in[19];
    const float* mlp_b1    = (const float*)d_in[20];
    const float* mlp_w2    = (const float*)d_in[21];
    const float* mlp_b2    = (const float*)d_in[22];
    const float* lnout_g   = (const float*)d_in[23];
    const float* lnout_b   = (const float*)d_in[24];
    const float* head_w    = (const float*)d_in[25];
    const float* head_b    = (const float*)d_in[26];

    // resolve device-global scratch
    #define GETP(sym, var, type) void* _p_##var; cudaGetSymbolAddress(&_p_##var, sym); type* var = (type*)_p_##var
    GETP(g_x, bx, float);       GETP(g_xn, bxn, float);
    GETP(g_zp, bzp, float);     GETP(g_dt, bdt, float);
    GETP(g_u, bu, float);
    GETP(g_semb, bsemb, float); GETP(g_thid, bthid, float); GETP(g_temb, btemb, float);
    GETP(g_xnh, bxnh, bf16);    GETP(g_xnl, bxnl, bf16);
    GETP(g_yh, byh, bf16);      GETP(g_yl, byl, bf16);
    GETP(g_hidh, bhidh, bf16);  GETP(g_hidl, bhidl, bf16);
    GETP(g_wzp_h, wzph, bf16);  GETP(g_wzp_l, wzpl, bf16);
    GETP(g_wout_h, wouth, bf16);GETP(g_wout_l, woutl, bf16);
    GETP(g_wm1_h, wm1h, bf16);  GETP(g_wm1_l, wm1l, bf16);
    GETP(g_wm2_h, wm2h, bf16);  GETP(g_wm2_l, wm2l, bf16);
    GETP(g_whd_h, whdh, bf16);  GETP(g_whd_l, whdl, bf16);
    #undef GETP

    cudaFuncSetAttribute(gemm_bf<0,false,0>, cudaFuncAttributeMaxDynamicSharedMemorySize, GSMEM);
    cudaFuncSetAttribute(gemm_bf<0,false,1>, cudaFuncAttributeMaxDynamicSharedMemorySize, GSMEM);
    cudaFuncSetAttribute(gemm_bf<2,true, 2>, cudaFuncAttributeMaxDynamicSharedMemorySize, GSMEM);
    cudaFuncSetAttribute(gemm_bf<0,true, 1>, cudaFuncAttributeMaxDynamicSharedMemorySize, GSMEM);
    cudaFuncSetAttribute(gemm_bf<0,true, 0>, cudaFuncAttributeMaxDynamicSharedMemorySize, GSMEM);

    // ---- weight conversion (once per call) ----
    {
        size_t n;
        n = (size_t)NDEPTH * ZPN * EDIM;
        build_wzp_kernel<<<(unsigned)((n + 255) / 256), 256>>>(z_w, p_w, wzph, wzpl);
        n = (size_t)NDEPTH * EDIM * EDIM;
        cvt_split_kernel<<<(unsigned)((n + 255) / 256), 256>>>(out_w, wouth, woutl, n);
        n = (size_t)NDEPTH * HD * EDIM;
        cvt_split_kernel<<<(unsigned)((n + 255) / 256), 256>>>(mlp_w1, wm1h, wm1l, n);
        n = (size_t)NDEPTH * EDIM * HD;
        cvt_split_kernel<<<(unsigned)((n + 255) / 256), 256>>>(mlp_w2, wm2h, wm2l, n);
        n = (size_t)VOC * EDIM;
        cvt_split_kernel<<<(unsigned)((n + 255) / 256), 256>>>(head_w, whdh, whdl, n);
    }

    // ---- embeddings ----
    semb_kernel<<<(NB*EDIM + 255)/256, 256>>>(timesteps, bsemb);
    time_mlp1<<<(NB*HD*32 + 255)/256, 256>>>(time_w1, time_b1, bsemb, bthid);
    time_mlp2<<<(NB*EDIM*32 + 255)/256, 256>>>(time_w2, time_b2, bthid, btemb);
    embed_kernel<<<(BL*EDIM + 255)/256, 256>>>(tokens, tok_emb, btemb, bx);

    for (int i = 0; i < NDEPTH; i++) {
        const bf16* wzph_i = wzph + (size_t)i * ZPN * EDIM;
        const bf16* wzpl_i = wzpl + (size_t)i * ZPN * EDIM;
        const bf16* wouth_i = wouth + (size_t)i * EDIM * EDIM;
        const bf16* woutl_i = woutl + (size_t)i * EDIM * EDIM;
        const bf16* wm1h_i = wm1h + (size_t)i * HD * EDIM;
        const bf16* wm1l_i = wm1l + (size_t)i * HD * EDIM;
        const bf16* wm2h_i = wm2h + (size_t)i * EDIM * HD;
        const bf16* wm2l_i = wm2l + (size_t)i * EDIM * HD;
        const float* cwi  = conv_w + (size_t)i * EDIM * KC;
        const float* dtwi = dtp_w + (size_t)i * EDIM * RD;
        const float* dtbi = dtp_b + (size_t)i * EDIM;
        const float* ali  = A_log + (size_t)i * EDIM * NS;
        const float* dpi  = D_param + (size_t)i * EDIM;
        const float* b1i  = mlp_b1 + (size_t)i * HD;
        const float* b2i  = mlp_b2 + (size_t)i * EDIM;

        ln_kernel<<<BL, 256>>>(bx, bxn, bxnh, bxnl, ln1_g + i*EDIM, ln1_b + i*EDIM);
        // fused z+params: zp = xn @ [z_w; p_w]^T  (N=896)
        gemm_bf<0,false,0><<<dim3(BL/128, ZPN/128), 256, GSMEM>>>(
            bxnh, bxnl, wzph_i, wzpl_i, EDIM, nullptr, bzp, nullptr, nullptr, ZPN, ZPN);
        // dt = softplus(zp[:, 768:816] @ dtp_w^T + b)  (SIMT, K=48)
        gemm_tn<1,true,false><<<dim3(EDIM/128, BL/128), 256>>>(
            bzp + EDIM, ZPN, dtwi, RD, dtbi, bdt, EDIM, BL, EDIM, RD);
        conv_silu<<<(BL*EDIM + 255)/256, 256>>>(bxn, cwi, bu);
        scan_kernel<<<(NB*EDIM*NS + 255)/256, 256>>>(ali, dpi, bdt, bu, bzp, byh, byl);
        // x += y @ out_w^T
        gemm_bf<0,false,1><<<dim3(BL/128, EDIM/128), 256, GSMEM>>>(
            byh, byl, wouth_i, woutl_i, EDIM, nullptr, bx, nullptr, nullptr, EDIM, EDIM);
        ln_kernel<<<BL, 256>>>(bx, bxn, bxnh, bxnl, ln2_g + i*EDIM, ln2_b + i*EDIM);
        // hid = gelu(xn @ w1^T + b1) -> bf16 hi/lo
        gemm_bf<2,true,2><<<dim3(BL/128, HD/128), 256, GSMEM>>>(
            bxnh, bxnl, wm1h_i, wm1l_i, EDIM, b1i, nullptr, bhidh, bhidl, HD, HD);
        // x += hid @ w2^T + b2
        gemm_bf<0,true,1><<<dim3(BL/128, EDIM/128), 256, GSMEM>>>(
            bhidh, bhidl, wm2h_i, wm2l_i, HD, b2i, bx, nullptr, nullptr, EDIM, EDIM);
    }

    ln_kernel<<<BL, 256>>>(bx, bxn, bxnh, bxnl, lnout_g, lnout_b);
    // logits = xn @ head_w^T + head_b
    gemm_bf<0,true,0><<<dim3(BL/128, VOC/128), 256, GSMEM>>>(
        bxnh, bxnl, whdh, whdl, EDIM, head_b, (float*)d_out, nullptr, nullptr, VOC, VOC);
}